// round 3
// baseline (speedup 1.0000x reference)
#include <cuda_runtime.h>

// eTofts DCE-MRI forward model — chunked-time smem staging for high occupancy.
// Inputs (metadata order): param [B,3] f32, T10 [B,1] f32, cp [B,T] f32.
// Output: [B,T] f32.
//
// CTA = 256 threads = 256 rows. Time axis processed in 4 chunks of 28:
//   stage chunk (coalesced float4 global -> smem transpose)
//   sequential IIR scan + signal equation in place (register-carried state u)
//   coalesced float4 store from smem
// smem = 256 x 29 floats = 29 KB -> ~8 CTAs/SM (vs 7x64-thread before).

#define TT    112
#define ROWS  256
#define TCH   28
#define NCH   4
#define SROW  29          // odd stride: conflict-free row scan
#define F4PT  7           // float4 per thread per phase (256*28/4/256)

__device__ __forceinline__ float ex2f(float x) {
    float y;
    asm("ex2.approx.ftz.f32 %0, %1;" : "=f"(y) : "f"(x));
    return y;
}
__device__ __forceinline__ float rcpf(float x) {
    float y;
    asm("rcp.approx.ftz.f32 %0, %1;" : "=f"(y) : "f"(x));
    return y;
}

__global__ __launch_bounds__(ROWS) void etofts_kernel(
    const float* __restrict__ param,
    const float* __restrict__ T10,
    const float* __restrict__ cp,
    float* __restrict__ out)
{
    __shared__ float tile[ROWS * SROW];
    const int tid  = threadIdx.x;
    const int row0 = blockIdx.x * ROWS;
    const int row  = row0 + tid;

    // ---- per-row constants ----
    const float p0  = param[row * 3 + 0];
    const float p1  = param[row * 3 + 1];
    const float p2  = param[row * 3 + 2];
    const float t10 = T10[row];

    const float ktrans = fminf(fmaxf(p0 * 0.2f, 1e-5f),   0.2f);
    const float vp     = fminf(fmaxf(p1 * 0.1f, 0.0005f), 0.1f);
    const float ve     = fminf(fmaxf(p2 * 0.6f, 0.04f),   0.6f);

    const float DELTT = 0.075f;                 // 4.5/60
    const float LOG2E = 1.4426950408889634f;
    const float TR    = 0.005f;
    const float SINA  = 0.25881904510252074f;   // sin(15 deg)
    const float COSA  = 0.9659258262890683f;    // cos(15 deg)

    const float decay = ex2f(-(ktrans / ve) * (DELTT * LOG2E));
    const float c1    = -(TR * 4.5f * LOG2E);   // log2-domain coeff of ct
    const float c0    = -(TR * LOG2E) * rcpf(t10);
    const float b_cp  = c1 * vp;                // coeff of cp[t]
    const float b_u   = c1 * ktrans * DELTT;    // coeff of scaled IIR state u
    const float numA  = 20.0f * SINA;

    const float4* cpb  = (const float4*)(cp  + (size_t)row0 * TT);
    float4*       outb = (float4*)      (out + (size_t)row0 * TT);

    float u = 0.0f;                             // IIR state, carried across chunks

    #pragma unroll 1
    for (int ch = 0; ch < NCH; ch++) {
        // ---- stage chunk: global -> smem (coalesced float4) ----
        #pragma unroll
        for (int i = 0; i < F4PT; i++) {
            unsigned j = i * ROWS + tid;
            unsigned r = j / F4PT;
            unsigned k = j - r * F4PT;
            float4 v = cpb[r * (TT / 4) + ch * F4PT + k];
            float* d = &tile[r * SROW + k * 4];
            d[0] = v.x; d[1] = v.y; d[2] = v.z; d[3] = v.w;
        }
        __syncthreads();

        // ---- sequential scan over this chunk, compute in place ----
        float* myrow = &tile[tid * SROW];
        #pragma unroll
        for (int t = 0; t < TCH; t++) {
            float cpt = myrow[t];
            u = fmaf(u, decay, cpt);                          // u = c/DELTT recurrence
            float arg = fmaf(b_cp, cpt, fmaf(b_u, u, c0));    // log2(E)
            float E   = ex2f(arg);
            float num = fmaf(E, -numA, numA);                 // 20*sinA*(1-E)
            float den = fmaf(E, -COSA, 1.0f);                 // 1 - cosA*E
            myrow[t]  = num * rcpf(den);
        }
        __syncthreads();

        // ---- store chunk: smem -> global (coalesced float4) ----
        #pragma unroll
        for (int i = 0; i < F4PT; i++) {
            unsigned j = i * ROWS + tid;
            unsigned r = j / F4PT;
            unsigned k = j - r * F4PT;
            const float* s = &tile[r * SROW + k * 4];
            outb[r * (TT / 4) + ch * F4PT + k] = make_float4(s[0], s[1], s[2], s[3]);
        }
        __syncthreads();   // tile reused next chunk
    }
}

extern "C" void kernel_launch(void* const* d_in, const int* in_sizes, int n_in,
                              void* d_out, int out_size)
{
    const float* param = (const float*)d_in[0];
    const float* T10   = (const float*)d_in[1];
    const float* cp    = (const float*)d_in[2];
    float*       out   = (float*)d_out;

    const int B = in_sizes[1];          // T10 has B elements
    etofts_kernel<<<B / ROWS, ROWS>>>(param, T10, cp, out);
}

// round 4
// speedup vs baseline: 1.2576x; 1.2576x over previous
#include <cuda_runtime.h>

// eTofts DCE-MRI forward model — warp-per-row parallel scan, no smem, no barriers.
// Inputs (metadata order): param [B,3] f32, T10 [B,1] f32, cp [B,T] f32.
// Output: [B,T] f32.
//
// One warp per row. Lane s (s<28) owns float4 = timesteps [4s, 4s+4).
// IIR u[t] = u[t-1]*d + cp[t] solved as:
//   local scan (3 FMA) -> warp scan of end-states with factor d^4 (5 shuffles)
//   -> per-element correction u_j = l_j + U0 * d^(j+1).
// All global traffic is one coalesced LDG.128 + STG.128 per lane.

#define TT 112

__device__ __forceinline__ float ex2f(float x) {
    float y;
    asm("ex2.approx.ftz.f32 %0, %1;" : "=f"(y) : "f"(x));
    return y;
}
__device__ __forceinline__ float rcpf(float x) {
    float y;
    asm("rcp.approx.ftz.f32 %0, %1;" : "=f"(y) : "f"(x));
    return y;
}

__global__ __launch_bounds__(256) void etofts_kernel(
    const float* __restrict__ param,
    const float* __restrict__ T10,
    const float* __restrict__ cp,
    float* __restrict__ out)
{
    const int lane = threadIdx.x & 31;
    const int row  = (blockIdx.x * blockDim.x + threadIdx.x) >> 5;
    const bool active = lane < (TT / 4);   // 28 active lanes per row

    // ---- per-row constants (same address across lanes -> broadcast load) ----
    const float p0  = __ldg(&param[row * 3 + 0]);
    const float p1  = __ldg(&param[row * 3 + 1]);
    const float p2  = __ldg(&param[row * 3 + 2]);
    const float t10 = __ldg(&T10[row]);

    const float ktrans = fminf(fmaxf(p0 * 0.2f, 1e-5f),   0.2f);
    const float vp     = fminf(fmaxf(p1 * 0.1f, 0.0005f), 0.1f);
    const float ve     = fminf(fmaxf(p2 * 0.6f, 0.04f),   0.6f);

    const float DELTT = 0.075f;                 // 4.5/60
    const float LOG2E = 1.4426950408889634f;
    const float TR    = 0.005f;
    const float SINA  = 0.25881904510252074f;   // sin(15 deg)
    const float COSA  = 0.9659258262890683f;    // cos(15 deg)

    const float d   = ex2f(-(ktrans * rcpf(ve)) * (DELTT * LOG2E));
    const float c1  = -(TR * 4.5f * LOG2E);
    const float c0  = -(TR * LOG2E) * rcpf(t10);
    const float b_cp = c1 * vp;                 // coeff of cp[t]
    const float b_u  = c1 * ktrans * DELTT;     // coeff of scaled IIR state u
    const float numA = 20.0f * SINA;

    // powers of d
    const float d2  = d  * d;
    const float d3  = d2 * d;
    const float d4  = d2 * d2;
    const float d8  = d4 * d4;
    const float d16 = d8 * d8;
    const float d32 = d16 * d16;
    const float d64 = d32 * d32;

    // ---- coalesced load: lane s gets timesteps [4s, 4s+4) ----
    const float4* rowp = (const float4*)(cp + (size_t)row * TT);
    float4 v = make_float4(0.f, 0.f, 0.f, 0.f);
    if (active) v = __ldg(&rowp[lane]);

    // ---- local inclusive scan of 4 elements ----
    const float l0 = v.x;
    const float l1 = fmaf(d, l0, v.y);
    const float l2 = fmaf(d, l1, v.z);
    const float l3 = fmaf(d, l2, v.w);

    // ---- warp scan of segment end-states with factor d^4 ----
    float Bv = l3;
    float t;
    t = __shfl_up_sync(0xffffffffu, Bv, 1);  if (lane >= 1)  Bv = fmaf(t, d4,  Bv);
    t = __shfl_up_sync(0xffffffffu, Bv, 2);  if (lane >= 2)  Bv = fmaf(t, d8,  Bv);
    t = __shfl_up_sync(0xffffffffu, Bv, 4);  if (lane >= 4)  Bv = fmaf(t, d16, Bv);
    t = __shfl_up_sync(0xffffffffu, Bv, 8);  if (lane >= 8)  Bv = fmaf(t, d32, Bv);
    t = __shfl_up_sync(0xffffffffu, Bv, 16); if (lane >= 16) Bv = fmaf(t, d64, Bv);

    float U0 = __shfl_up_sync(0xffffffffu, Bv, 1);   // state entering this segment
    if (lane == 0) U0 = 0.0f;

    // ---- correction: full IIR state per element ----
    const float u0 = fmaf(U0, d,  l0);
    const float u1 = fmaf(U0, d2, l1);
    const float u2 = fmaf(U0, d3, l2);
    const float u3 = fmaf(U0, d4, l3);

    // ---- signal equation ----
    float4 r;
    {
        float E, num, den;
        E = ex2f(fmaf(b_cp, v.x, fmaf(b_u, u0, c0)));
        num = fmaf(E, -numA, numA); den = fmaf(E, -COSA, 1.0f); r.x = num * rcpf(den);
        E = ex2f(fmaf(b_cp, v.y, fmaf(b_u, u1, c0)));
        num = fmaf(E, -numA, numA); den = fmaf(E, -COSA, 1.0f); r.y = num * rcpf(den);
        E = ex2f(fmaf(b_cp, v.z, fmaf(b_u, u2, c0)));
        num = fmaf(E, -numA, numA); den = fmaf(E, -COSA, 1.0f); r.z = num * rcpf(den);
        E = ex2f(fmaf(b_cp, v.w, fmaf(b_u, u3, c0)));
        num = fmaf(E, -numA, numA); den = fmaf(E, -COSA, 1.0f); r.w = num * rcpf(den);
    }

    // ---- coalesced store ----
    if (active) ((float4*)(out + (size_t)row * TT))[lane] = r;
}

extern "C" void kernel_launch(void* const* d_in, const int* in_sizes, int n_in,
                              void* d_out, int out_size)
{
    const float* param = (const float*)d_in[0];
    const float* T10   = (const float*)d_in[1];
    const float* cp    = (const float*)d_in[2];
    float*       out   = (float*)d_out;

    const int B = in_sizes[1];          // T10 has B elements
    // one warp per row, 8 warps per CTA
    etofts_kernel<<<B / 8, 256>>>(param, T10, cp, out);
}

// round 5
// speedup vs baseline: 1.4177x; 1.1274x over previous
#include <cuda_runtime.h>

// eTofts DCE-MRI forward model.
// Round 4: (a) per-row constants hoisted into a pre-pass kernel (4MB device
// scratch), (b) 2 rows per warp / 8 timesteps per lane with width-16
// segmented warp scan. Targets issue-rate (was 60.6%), DRAM was only 57%.

#define TT    112
#define BMAX  262144

__device__ __forceinline__ float ex2f(float x) {
    float y;
    asm("ex2.approx.ftz.f32 %0, %1;" : "=f"(y) : "f"(x));
    return y;
}
__device__ __forceinline__ float rcpf(float x) {
    float y;
    asm("rcp.approx.ftz.f32 %0, %1;" : "=f"(y) : "f"(x));
    return y;
}

// per-row constants: {decay d, b_cp, b_u, c0}
__device__ float4 g_cst[BMAX];

__global__ __launch_bounds__(256) void etofts_prep(
    const float* __restrict__ param,
    const float* __restrict__ T10,
    int B)
{
    const int i = blockIdx.x * blockDim.x + threadIdx.x;
    if (i >= B) return;

    const float p0  = __ldg(&param[3 * i + 0]);
    const float p1  = __ldg(&param[3 * i + 1]);
    const float p2  = __ldg(&param[3 * i + 2]);
    const float t10 = __ldg(&T10[i]);

    const float ktrans = fminf(fmaxf(p0 * 0.2f, 1e-5f),   0.2f);
    const float vp     = fminf(fmaxf(p1 * 0.1f, 0.0005f), 0.1f);
    const float ve     = fminf(fmaxf(p2 * 0.6f, 0.04f),   0.6f);

    const float DELTT = 0.075f;                 // 4.5/60
    const float LOG2E = 1.4426950408889634f;
    const float TR    = 0.005f;

    const float d    = ex2f(-(ktrans * rcpf(ve)) * (DELTT * LOG2E));
    const float c1   = -(TR * 4.5f * LOG2E);
    const float c0   = -(TR * LOG2E) * rcpf(t10);
    const float b_cp = c1 * vp;
    const float b_u  = c1 * ktrans * DELTT;

    g_cst[i] = make_float4(d, b_cp, b_u, c0);
}

__global__ __launch_bounds__(256) void etofts_main(
    const float* __restrict__ cp,
    float* __restrict__ out)
{
    const int lane = threadIdx.x & 31;
    const int w    = (blockIdx.x * blockDim.x + threadIdx.x) >> 5;  // warp id
    const int half = lane >> 4;          // 0 or 1: which row of this warp
    const int sl   = lane & 15;          // lane within 16-wide segment
    const bool active = sl < (TT / 8);   // 14 active lanes per segment

    const int row = 2 * w + half;

    // per-row constants (broadcast within each half-warp)
    const float4 cst = g_cst[row];
    const float d    = cst.x;
    const float b_cp = cst.y;
    const float b_u  = cst.z;
    const float c0   = cst.w;

    const float SINA = 0.25881904510252074f;    // sin(15 deg)
    const float COSA = 0.9659258262890683f;     // cos(15 deg)
    const float numA = 20.0f * SINA;

    // powers of d
    const float d2  = d   * d;
    const float d3  = d2  * d;
    const float d4  = d2  * d2;
    const float d8  = d4  * d4;
    const float d16 = d8  * d8;
    const float d32 = d16 * d16;
    const float d64 = d32 * d32;

    // scan weights (zero where shfl_up would clamp to own value)
    const float w1 = (sl >= 1) ? d8  : 0.0f;
    const float w2 = (sl >= 2) ? d16 : 0.0f;
    const float w4 = (sl >= 4) ? d32 : 0.0f;
    const float w8 = (sl >= 8) ? d64 : 0.0f;

    // lane owns timesteps [8*sl, 8*sl+8) of its row
    const float4* rowp = (const float4*)(cp + (size_t)row * TT);
    float4 va = make_float4(0.f, 0.f, 0.f, 0.f);
    float4 vb = make_float4(0.f, 0.f, 0.f, 0.f);
    if (active) {
        va = __ldg(&rowp[2 * sl]);
        vb = __ldg(&rowp[2 * sl + 1]);
    }

    // local inclusive scan of 8 elements
    const float l0 = va.x;
    const float l1 = fmaf(d, l0, va.y);
    const float l2 = fmaf(d, l1, va.z);
    const float l3 = fmaf(d, l2, va.w);
    const float l4 = fmaf(d, l3, vb.x);
    const float l5 = fmaf(d, l4, vb.y);
    const float l6 = fmaf(d, l5, vb.z);
    const float l7 = fmaf(d, l6, vb.w);

    // width-16 segmented warp scan of segment end-states (factor d^8 per hop)
    float Bv = l7;
    float t;
    t = __shfl_up_sync(0xffffffffu, Bv, 1, 16); Bv = fmaf(t, w1, Bv);
    t = __shfl_up_sync(0xffffffffu, Bv, 2, 16); Bv = fmaf(t, w2, Bv);
    t = __shfl_up_sync(0xffffffffu, Bv, 4, 16); Bv = fmaf(t, w4, Bv);
    t = __shfl_up_sync(0xffffffffu, Bv, 8, 16); Bv = fmaf(t, w8, Bv);

    float U0 = __shfl_up_sync(0xffffffffu, Bv, 1, 16);  // state entering segment
    if (sl == 0) U0 = 0.0f;

    // full IIR state per element: first 4 via powers, last 4 via recurrence
    const float u0 = fmaf(U0, d,  l0);
    const float u1 = fmaf(U0, d2, l1);
    const float u2 = fmaf(U0, d3, l2);
    const float u3 = fmaf(U0, d4, l3);
    const float u4 = fmaf(d, u3, vb.x);
    const float u5 = fmaf(d, u4, vb.y);
    const float u6 = fmaf(d, u5, vb.z);
    const float u7 = fmaf(d, u6, vb.w);

    // signal equation
    float4 ra, rb;
    {
        float E, num, den;
        E = ex2f(fmaf(b_cp, va.x, fmaf(b_u, u0, c0)));
        num = fmaf(E, -numA, numA); den = fmaf(E, -COSA, 1.0f); ra.x = num * rcpf(den);
        E = ex2f(fmaf(b_cp, va.y, fmaf(b_u, u1, c0)));
        num = fmaf(E, -numA, numA); den = fmaf(E, -COSA, 1.0f); ra.y = num * rcpf(den);
        E = ex2f(fmaf(b_cp, va.z, fmaf(b_u, u2, c0)));
        num = fmaf(E, -numA, numA); den = fmaf(E, -COSA, 1.0f); ra.z = num * rcpf(den);
        E = ex2f(fmaf(b_cp, va.w, fmaf(b_u, u3, c0)));
        num = fmaf(E, -numA, numA); den = fmaf(E, -COSA, 1.0f); ra.w = num * rcpf(den);
        E = ex2f(fmaf(b_cp, vb.x, fmaf(b_u, u4, c0)));
        num = fmaf(E, -numA, numA); den = fmaf(E, -COSA, 1.0f); rb.x = num * rcpf(den);
        E = ex2f(fmaf(b_cp, vb.y, fmaf(b_u, u5, c0)));
        num = fmaf(E, -numA, numA); den = fmaf(E, -COSA, 1.0f); rb.y = num * rcpf(den);
        E = ex2f(fmaf(b_cp, vb.z, fmaf(b_u, u6, c0)));
        num = fmaf(E, -numA, numA); den = fmaf(E, -COSA, 1.0f); rb.z = num * rcpf(den);
        E = ex2f(fmaf(b_cp, vb.w, fmaf(b_u, u7, c0)));
        num = fmaf(E, -numA, numA); den = fmaf(E, -COSA, 1.0f); rb.w = num * rcpf(den);
    }

    if (active) {
        float4* outp = (float4*)(out + (size_t)row * TT);
        outp[2 * sl]     = ra;
        outp[2 * sl + 1] = rb;
    }
}

extern "C" void kernel_launch(void* const* d_in, const int* in_sizes, int n_in,
                              void* d_out, int out_size)
{
    const float* param = (const float*)d_in[0];
    const float* T10   = (const float*)d_in[1];
    const float* cp    = (const float*)d_in[2];
    float*       out   = (float*)d_out;

    const int B = in_sizes[1];          // T10 has B elements

    etofts_prep<<<(B + 255) / 256, 256>>>(param, T10, B);

    // 2 rows per warp -> B/2 warps -> B*16 threads
    const int threads = 256;
    const int blocks  = (B / 2) * 32 / threads;
    etofts_main<<<blocks, threads>>>(cp, out);
}

// round 7
// speedup vs baseline: 1.4541x; 1.0257x over previous
#include <cuda_runtime.h>

// eTofts DCE-MRI forward model — single fused kernel.
// 4 rows per warp (two row-pairs), 8 timesteps per lane, width-16 segmented
// warp scan. Per-row constants computed redundantly in-warp (lane&3) and
// broadcast via shuffles — no pre-pass kernel, no scratch.
// All global traffic: 4x LDG.128 + 4x STG.128 per lane, streaming hints.

#define TT 112

__device__ __forceinline__ float ex2f(float x) {
    float y;
    asm("ex2.approx.ftz.f32 %0, %1;" : "=f"(y) : "f"(x));
    return y;
}
__device__ __forceinline__ float rcpf(float x) {
    float y;
    asm("rcp.approx.ftz.f32 %0, %1;" : "=f"(y) : "f"(x));
    return y;
}

__global__ __launch_bounds__(256) void etofts_kernel(
    const float* __restrict__ param,
    const float* __restrict__ T10,
    const float* __restrict__ cp,
    float* __restrict__ out)
{
    const int lane = threadIdx.x & 31;
    const int w    = (blockIdx.x * blockDim.x + threadIdx.x) >> 5;  // warp id
    const int half = lane >> 4;          // which row of the pair
    const int sl   = lane & 15;          // lane within 16-wide segment
    const bool active = sl < (TT / 8);   // 14 active lanes per segment

    const int rbase = 4 * w;

    // ---- in-warp constants: every lane computes row rbase + (lane&3) ----
    const int crow = rbase + (lane & 3);
    const float p0  = __ldg(&param[3 * crow + 0]);
    const float p1  = __ldg(&param[3 * crow + 1]);
    const float p2  = __ldg(&param[3 * crow + 2]);
    const float t10 = __ldg(&T10[crow]);

    const float ktrans = fminf(fmaxf(p0 * 0.2f, 1e-5f),   0.2f);
    const float vp     = fminf(fmaxf(p1 * 0.1f, 0.0005f), 0.1f);
    const float ve     = fminf(fmaxf(p2 * 0.6f, 0.04f),   0.6f);

    const float DELTT = 0.075f;                 // 4.5/60
    const float LOG2E = 1.4426950408889634f;
    const float TR    = 0.005f;
    const float SINA  = 0.25881904510252074f;   // sin(15 deg)
    const float COSA  = 0.9659258262890683f;    // cos(15 deg)
    const float numA  = 20.0f * SINA;

    const float dv    = ex2f(-(ktrans * rcpf(ve)) * (DELTT * LOG2E));
    const float c1    = -(TR * 4.5f * LOG2E);
    const float c0v   = -(TR * LOG2E) * rcpf(t10);
    const float bcpv  = c1 * vp;
    const float buv   = c1 * ktrans * DELTT;

    // ---- issue all global loads up front (MLP = 4 x LDG.128) ----
    const float4* rp0 = (const float4*)(cp + (size_t)(rbase + half)     * TT);
    const float4* rp1 = (const float4*)(cp + (size_t)(rbase + 2 + half) * TT);
    float4 va0, vb0, va1, vb1;
    va0 = vb0 = va1 = vb1 = make_float4(0.f, 0.f, 0.f, 0.f);
    if (active) {
        va0 = __ldcs(&rp0[2 * sl]);
        vb0 = __ldcs(&rp0[2 * sl + 1]);
        va1 = __ldcs(&rp1[2 * sl]);
        vb1 = __ldcs(&rp1[2 * sl + 1]);
    }

    #pragma unroll
    for (int p = 0; p < 2; p++) {
        const float4 va = p ? va1 : va0;
        const float4 vb = p ? vb1 : vb0;

        // broadcast this pair's constants from lane 2p+half
        const int src = 2 * p + half;
        const float d    = __shfl_sync(0xffffffffu, dv,   src);
        const float b_cp = __shfl_sync(0xffffffffu, bcpv, src);
        const float b_u  = __shfl_sync(0xffffffffu, buv,  src);
        const float c0   = __shfl_sync(0xffffffffu, c0v,  src);

        // powers of d
        const float d2  = d   * d;
        const float d3  = d2  * d;
        const float d4  = d2  * d2;
        const float d8  = d4  * d4;
        const float d16 = d8  * d8;
        const float d32 = d16 * d16;
        const float d64 = d32 * d32;

        const float w1 = (sl >= 1) ? d8  : 0.0f;
        const float w2 = (sl >= 2) ? d16 : 0.0f;
        const float w4 = (sl >= 4) ? d32 : 0.0f;
        const float w8 = (sl >= 8) ? d64 : 0.0f;

        // local inclusive scan of 8 elements
        const float l0 = va.x;
        const float l1 = fmaf(d, l0, va.y);
        const float l2 = fmaf(d, l1, va.z);
        const float l3 = fmaf(d, l2, va.w);
        const float l4 = fmaf(d, l3, vb.x);
        const float l5 = fmaf(d, l4, vb.y);
        const float l6 = fmaf(d, l5, vb.z);
        const float l7 = fmaf(d, l6, vb.w);

        // width-16 segmented warp scan of end-states (factor d^8 per hop)
        float Bv = l7;
        float t;
        t = __shfl_up_sync(0xffffffffu, Bv, 1, 16); Bv = fmaf(t, w1, Bv);
        t = __shfl_up_sync(0xffffffffu, Bv, 2, 16); Bv = fmaf(t, w2, Bv);
        t = __shfl_up_sync(0xffffffffu, Bv, 4, 16); Bv = fmaf(t, w4, Bv);
        t = __shfl_up_sync(0xffffffffu, Bv, 8, 16); Bv = fmaf(t, w8, Bv);

        float U0 = __shfl_up_sync(0xffffffffu, Bv, 1, 16);
        if (sl == 0) U0 = 0.0f;

        // full IIR state per element
        const float u0 = fmaf(U0, d,  l0);
        const float u1 = fmaf(U0, d2, l1);
        const float u2 = fmaf(U0, d3, l2);
        const float u3 = fmaf(U0, d4, l3);
        const float u4 = fmaf(d, u3, vb.x);
        const float u5 = fmaf(d, u4, vb.y);
        const float u6 = fmaf(d, u5, vb.z);
        const float u7 = fmaf(d, u6, vb.w);

        // signal equation
        float4 ra, rb;
        float E, num, den;
        E = ex2f(fmaf(b_cp, va.x, fmaf(b_u, u0, c0)));
        num = fmaf(E, -numA, numA); den = fmaf(E, -COSA, 1.0f); ra.x = num * rcpf(den);
        E = ex2f(fmaf(b_cp, va.y, fmaf(b_u, u1, c0)));
        num = fmaf(E, -numA, numA); den = fmaf(E, -COSA, 1.0f); ra.y = num * rcpf(den);
        E = ex2f(fmaf(b_cp, va.z, fmaf(b_u, u2, c0)));
        num = fmaf(E, -numA, numA); den = fmaf(E, -COSA, 1.0f); ra.z = num * rcpf(den);
        E = ex2f(fmaf(b_cp, va.w, fmaf(b_u, u3, c0)));
        num = fmaf(E, -numA, numA); den = fmaf(E, -COSA, 1.0f); ra.w = num * rcpf(den);
        E = ex2f(fmaf(b_cp, vb.x, fmaf(b_u, u4, c0)));
        num = fmaf(E, -numA, numA); den = fmaf(E, -COSA, 1.0f); rb.x = num * rcpf(den);
        E = ex2f(fmaf(b_cp, vb.y, fmaf(b_u, u5, c0)));
        num = fmaf(E, -numA, numA); den = fmaf(E, -COSA, 1.0f); rb.y = num * rcpf(den);
        E = ex2f(fmaf(b_cp, vb.z, fmaf(b_u, u6, c0)));
        num = fmaf(E, -numA, numA); den = fmaf(E, -COSA, 1.0f); rb.z = num * rcpf(den);
        E = ex2f(fmaf(b_cp, vb.w, fmaf(b_u, u7, c0)));
        num = fmaf(E, -numA, numA); den = fmaf(E, -COSA, 1.0f); rb.w = num * rcpf(den);

        if (active) {
            float4* outp = (float4*)(out + (size_t)(rbase + 2 * p + half) * TT);
            __stcs(&outp[2 * sl],     ra);
            __stcs(&outp[2 * sl + 1], rb);
        }
    }
}

extern "C" void kernel_launch(void* const* d_in, const int* in_sizes, int n_in,
                              void* d_out, int out_size)
{
    const float* param = (const float*)d_in[0];
    const float* T10   = (const float*)d_in[1];
    const float* cp    = (const float*)d_in[2];
    float*       out   = (float*)d_out;

    const int B = in_sizes[1];          // T10 has B elements
    // 4 rows per warp, 8 warps per CTA
    etofts_kernel<<<B / 32, 256>>>(param, T10, cp, out);
}